// round 4
// baseline (speedup 1.0000x reference)
#include <cuda_runtime.h>

#define Bb 8
#define Nn 1024
#define Ee 512
#define Hh 8
#define Dd 64
#define NEGV -1000000000.0f

typedef unsigned long long u64;

// ---------------------------------------------------------------------------
// Scratch (device globals: allocation-free per harness rules)
// NOTE: only ever referenced from DEVICE code (selector ints from host) —
// passing these symbols as host-side kernel args was the R3 bug.
// ---------------------------------------------------------------------------
__device__ float g_q[Bb*Hh*Nn*Dd];     // [b,h,n,d]
__device__ float g_k[Bb*Hh*Nn*Dd];
__device__ float g_v[Bb*Hh*Nn*Dd];
__device__ float g_attn[Bb*Nn*Ee];     // flat [m = b*N+n, c = h*64+d]
__device__ unsigned char g_code[Bb*Nn*Nn];

// ---------------------------------------------------------------------------
// Packed fp32x2 helpers (Blackwell family FFMA2 path)
// ---------------------------------------------------------------------------
__device__ __forceinline__ void fma2(u64& d, u64 a, u64 b) {
    asm("fma.rn.f32x2 %0, %1, %2, %3;" : "=l"(d) : "l"(a), "l"(b), "l"(d));
}
__device__ __forceinline__ void mul2(u64& d, u64 a, u64 b) {
    asm("mul.rn.f32x2 %0, %1, %2;" : "=l"(d) : "l"(a), "l"(b));
}
__device__ __forceinline__ u64 pack2f(float lo, float hi) {
    u64 r; asm("mov.b64 %0, {%1,%2};" : "=l"(r) : "f"(lo), "f"(hi)); return r;
}
__device__ __forceinline__ float2 unpack2(u64 v) {
    float2 f; asm("mov.b64 {%0,%1}, %2;" : "=f"(f.x), "=f"(f.y) : "l"(v)); return f;
}

// ---------------------------------------------------------------------------
// Mask precompute: code[b,i,j] = smallest head index that attends.
// ---------------------------------------------------------------------------
__device__ __forceinline__ unsigned char code_one(float d, int mk, int i, int j) {
    if (mk == 0) return (unsigned char)255;
    if (i == 0 || j == 0) return (unsigned char)0;
    unsigned char c = 0;
    c += (d >= 0.2f); c += (d >= 0.3f); c += (d >= 0.4f); c += (d >= 0.5f);
    c += (d >= 0.6f); c += (d >= 0.7f); c += (d >= 0.8f); c += (d >= 0.9f);
    return c;
}

__global__ __launch_bounds__(256) void code_kernel(const float* __restrict__ dist,
                                                   const int* __restrict__ mask) {
    int t = blockIdx.x * blockDim.x + threadIdx.x;
    int base = t * 4;
    int rem = base & (Nn*Nn - 1);
    int i = rem >> 10;
    int j0 = rem & (Nn - 1);
    float4 dv = *(const float4*)(dist + base);
    int4  mv = *(const int4*)(mask + base);
    uchar4 o;
    o.x = code_one(dv.x, mv.x, i, j0 + 0);
    o.y = code_one(dv.y, mv.y, i, j0 + 1);
    o.z = code_one(dv.z, mv.z, i, j0 + 2);
    o.w = code_one(dv.w, mv.w, i, j0 + 3);
    *(uchar4*)(g_code + base) = o;
}

// ---------------------------------------------------------------------------
// Unified GEMM: out = A[8192,512] . W[512,512]^T + bias, 64x64 tiles.
// f32x2 packed over k: smem rows hold k-pairs (u64), row stride 9 u64.
// a_sel: 0 = use Aext (harness pointer), 1 = use g_attn.
// out_mode: 0/1/2 = scatter into g_q/g_k/g_v ([b,h,n,d]); 3 = flat outext.
// ---------------------------------------------------------------------------
__global__ __launch_bounds__(256) void gemm64(const float* __restrict__ Aext,
                                              const float* __restrict__ W,
                                              const float* __restrict__ bias,
                                              float* __restrict__ outext,
                                              int a_sel, int out_mode) {
    __shared__ u64 As[64 * 9];
    __shared__ u64 Ws[64 * 9];
    float* asf = (float*)As;
    float* wsf = (float*)Ws;

    const float* A = (a_sel == 0) ? Aext : g_attn;
    float* out = (out_mode == 0) ? g_q : (out_mode == 1) ? g_k
                 : (out_mode == 2) ? g_v : outext;

    int tid = threadIdx.x;
    int ty = tid >> 4, tx = tid & 15;
    int m0 = blockIdx.x * 64, n0 = blockIdx.y * 64;
    int lrow = tid >> 2, lseg = tid & 3;

    const float* Ap = A + (m0 + lrow) * Ee + lseg * 4;
    const float* Wp = W + (n0 + lrow) * Ee + lseg * 4;

    u64 acc[4][4];
    #pragma unroll
    for (int i = 0; i < 4; i++)
        #pragma unroll
        for (int j = 0; j < 4; j++) acc[i][j] = 0ull;

    for (int kt = 0; kt < Ee / 16; kt++) {
        float4 a4 = *(const float4*)(Ap + kt * 16);
        float4 w4 = *(const float4*)(Wp + kt * 16);
        __syncthreads();
        *(float2*)(asf + lrow * 18 + lseg * 4 + 0) = make_float2(a4.x, a4.y);
        *(float2*)(asf + lrow * 18 + lseg * 4 + 2) = make_float2(a4.z, a4.w);
        *(float2*)(wsf + lrow * 18 + lseg * 4 + 0) = make_float2(w4.x, w4.y);
        *(float2*)(wsf + lrow * 18 + lseg * 4 + 2) = make_float2(w4.z, w4.w);
        __syncthreads();
        #pragma unroll
        for (int k2 = 0; k2 < 8; k2++) {
            u64 a2[4], b2[4];
            #pragma unroll
            for (int i = 0; i < 4; i++) a2[i] = As[(ty * 4 + i) * 9 + k2];
            #pragma unroll
            for (int j = 0; j < 4; j++) b2[j] = Ws[(tx + 16 * j) * 9 + k2];
            #pragma unroll
            for (int i = 0; i < 4; i++)
                #pragma unroll
                for (int j = 0; j < 4; j++)
                    fma2(acc[i][j], a2[i], b2[j]);
        }
    }

    #pragma unroll
    for (int j = 0; j < 4; j++) {
        int col = n0 + tx + 16 * j;
        float bj = bias[col];
        #pragma unroll
        for (int i = 0; i < 4; i++) {
            int m = m0 + ty * 4 + i;
            float2 f = unpack2(acc[i][j]);
            float val = f.x + f.y + bj;
            if (out_mode < 3) {
                int b_ = m >> 10, n = m & (Nn - 1);
                int h = col >> 6, d = col & 63;
                out[((((b_ << 3) + h) << 10) + n) * 64 + d] = val;
            } else {
                out[m * Ee + col] = val;
            }
        }
    }
}

// ---------------------------------------------------------------------------
// Flash attention, f32x2 packed over the contraction dims.
// smem rows: [64][33] u64 (66 floats). Thread (ty,tx): rows ty*4+i, cols tx+16j.
// Writes output directly in flat layout g_attn[m, h*64+d].
// ---------------------------------------------------------------------------
#define ROWU 33
#define ROWF 66
#define FL_QP 0
#define FL_KP (64 * ROWU)
#define FL_VT (2 * 64 * ROWU)
#define FL_PT (3 * 64 * ROWU)
#define FL_CS_BYTES (4 * 64 * ROWU * 8)
#define FL_SMEM (FL_CS_BYTES + 64 * 64)

__global__ __launch_bounds__(256) void flash_kernel() {
    extern __shared__ u64 smu[];
    u64* Qp = smu + FL_QP;
    u64* Kp = smu + FL_KP;
    u64* Vt = smu + FL_VT;
    u64* Pt = smu + FL_PT;
    float* Qf = (float*)Qp;
    float* Kf = (float*)Kp;
    float* Vf = (float*)Vt;
    float* Pf = (float*)Pt;
    unsigned char* Cs = (unsigned char*)smu + FL_CS_BYTES;

    int rb = blockIdx.x, h = blockIdx.y, b = blockIdx.z;
    const float* Qg = g_q + (((b * Hh + h) * Nn + rb * 64) * Dd);
    const float* Kg = g_k + ((b * Hh + h) * Nn) * Dd;
    const float* Vg = g_v + ((b * Hh + h) * Nn) * Dd;
    const unsigned char* code = g_code + (b * Nn + rb * 64) * Nn;

    int tid = threadIdx.x;
    int ty = tid >> 4, tx = tid & 15;

    #pragma unroll
    for (int l = 0; l < 4; l++) {
        int idx = tid + l * 256;
        int r = idx >> 4;
        int d0 = (idx & 15) << 2;
        float4 q4 = *(const float4*)(Qg + r * 64 + d0);
        *(float2*)(Qf + r * ROWF + d0 + 0) = make_float2(q4.x, q4.y);
        *(float2*)(Qf + r * ROWF + d0 + 2) = make_float2(q4.z, q4.w);
    }

    u64 acc[4][4];
    #pragma unroll
    for (int i = 0; i < 4; i++)
        #pragma unroll
        for (int j = 0; j < 4; j++) acc[i][j] = 0ull;
    float m_i[4], l_i[4];
    #pragma unroll
    for (int i = 0; i < 4; i++) { m_i[i] = -1e30f; l_i[i] = 0.0f; }

    for (int kb = 0; kb < Nn / 64; kb++) {
        __syncthreads();
        #pragma unroll
        for (int l = 0; l < 4; l++) {
            int idx = tid + l * 256;
            int c = idx >> 4;
            int d0 = (idx & 15) << 2;
            float4 k4 = *(const float4*)(Kg + (kb * 64 + c) * 64 + d0);
            *(float2*)(Kf + c * ROWF + d0 + 0) = make_float2(k4.x, k4.y);
            *(float2*)(Kf + c * ROWF + d0 + 2) = make_float2(k4.z, k4.w);
            float4 v4 = *(const float4*)(Vg + (kb * 64 + c) * 64 + d0);
            Vf[(d0 + 0) * ROWF + c] = v4.x;
            Vf[(d0 + 1) * ROWF + c] = v4.y;
            Vf[(d0 + 2) * ROWF + c] = v4.z;
            Vf[(d0 + 3) * ROWF + c] = v4.w;
        }
        {
            int r = tid >> 2;
            int s4 = (tid & 3) << 4;
            *(uint4*)(Cs + r * 64 + s4) = *(const uint4*)(code + r * Nn + kb * 64 + s4);
        }
        __syncthreads();

        u64 s2[4][4];
        #pragma unroll
        for (int i = 0; i < 4; i++)
            #pragma unroll
            for (int j = 0; j < 4; j++) s2[i][j] = 0ull;
        #pragma unroll
        for (int d2 = 0; d2 < 32; d2++) {
            u64 q2[4], k2[4];
            #pragma unroll
            for (int i = 0; i < 4; i++) q2[i] = Qp[(ty * 4 + i) * ROWU + d2];
            #pragma unroll
            for (int j = 0; j < 4; j++) k2[j] = Kp[(tx + 16 * j) * ROWU + d2];
            #pragma unroll
            for (int i = 0; i < 4; i++)
                #pragma unroll
                for (int j = 0; j < 4; j++)
                    fma2(s2[i][j], q2[i], k2[j]);
        }

        float s[4][4];
        #pragma unroll
        for (int i = 0; i < 4; i++)
            #pragma unroll
            for (int j = 0; j < 4; j++) {
                float2 f = unpack2(s2[i][j]);
                float v = (f.x + f.y) * 0.125f;
                unsigned cd = Cs[(ty * 4 + i) * 64 + tx + 16 * j];
                s[i][j] = ((unsigned)h >= cd) ? v : NEGV;
            }

        float corr[4], ps[4];
        #pragma unroll
        for (int i = 0; i < 4; i++) {
            float r = fmaxf(fmaxf(s[i][0], s[i][1]), fmaxf(s[i][2], s[i][3]));
            #pragma unroll
            for (int o = 8; o > 0; o >>= 1)
                r = fmaxf(r, __shfl_xor_sync(0xffffffffu, r, o));
            float mn = fmaxf(m_i[i], r);
            corr[i] = __expf(m_i[i] - mn);
            m_i[i] = mn;
            ps[i] = 0.0f;
        }
        #pragma unroll
        for (int i = 0; i < 4; i++)
            #pragma unroll
            for (int j = 0; j < 4; j++) {
                float p = __expf(s[i][j] - m_i[i]);
                ps[i] += p;
                Pf[(ty * 4 + i) * ROWF + tx + 16 * j] = p;
            }
        #pragma unroll
        for (int i = 0; i < 4; i++) {
            float r = ps[i];
            #pragma unroll
            for (int o = 8; o > 0; o >>= 1)
                r += __shfl_xor_sync(0xffffffffu, r, o);
            l_i[i] = l_i[i] * corr[i] + r;
            u64 c2 = pack2f(corr[i], corr[i]);
            #pragma unroll
            for (int j = 0; j < 4; j++) mul2(acc[i][j], acc[i][j], c2);
        }
        __syncthreads();

        #pragma unroll
        for (int c2 = 0; c2 < 32; c2++) {
            u64 p2[4], v2[4];
            #pragma unroll
            for (int i = 0; i < 4; i++) p2[i] = Pt[(ty * 4 + i) * ROWU + c2];
            #pragma unroll
            for (int j = 0; j < 4; j++) v2[j] = Vt[(tx + 16 * j) * ROWU + c2];
            #pragma unroll
            for (int i = 0; i < 4; i++)
                #pragma unroll
                for (int j = 0; j < 4; j++)
                    fma2(acc[i][j], p2[i], v2[j]);
        }
    }

    #pragma unroll
    for (int i = 0; i < 4; i++) {
        float inv = 1.0f / l_i[i];
        int n = rb * 64 + ty * 4 + i;
        float* op = g_attn + ((b << 10) + n) * Ee + (h << 6);
        #pragma unroll
        for (int j = 0; j < 4; j++) {
            float2 f = unpack2(acc[i][j]);
            op[tx + 16 * j] = (f.x + f.y) * inv;
        }
    }
}

// ---------------------------------------------------------------------------
extern "C" void kernel_launch(void* const* d_in, const int* in_sizes, int n_in,
                              void* d_out, int out_size) {
    const float* query = (const float*)d_in[0];
    const float* key   = (const float*)d_in[1];
    const float* value = (const float*)d_in[2];
    const float* dist  = (const float*)d_in[3];
    const int*   mask  = (const int*)d_in[4];
    const float* Wq = (const float*)d_in[5];
    const float* bq = (const float*)d_in[6];
    const float* Wk = (const float*)d_in[7];
    const float* bk = (const float*)d_in[8];
    const float* Wv = (const float*)d_in[9];
    const float* bv = (const float*)d_in[10];
    const float* Wo = (const float*)d_in[11];
    const float* bo = (const float*)d_in[12];
    float* out = (float*)d_out;

    cudaFuncSetAttribute(flash_kernel, cudaFuncAttributeMaxDynamicSharedMemorySize, FL_SMEM);

    // 1) mask code precompute
    code_kernel<<<(Bb * Nn * Nn) / (4 * 256), 256>>>(dist, mask);

    // 2) Q/K/V projections (device-side scatter into g_q/g_k/g_v)
    dim3 ggrid((Bb * Nn) / 64, Ee / 64);
    gemm64<<<ggrid, 256>>>(query, Wq, bq, nullptr, 0, 0);
    gemm64<<<ggrid, 256>>>(key,   Wk, bk, nullptr, 0, 1);
    gemm64<<<ggrid, 256>>>(value, Wv, bv, nullptr, 0, 2);

    // 3) flash attention -> flat g_attn (device global)
    flash_kernel<<<dim3(Nn / 64, Hh, Bb), 256, FL_SMEM>>>();

    // 4) output projection (A = g_attn selected device-side, flat out)
    gemm64<<<ggrid, 256>>>(nullptr, Wo, bo, out, 1, 3);
}

// round 5
// speedup vs baseline: 1.4583x; 1.4583x over previous
#include <cuda_runtime.h>
#include <cuda_bf16.h>

#define Bb 8
#define Nn 1024
#define Ee 512
#define Hh 8
#define Dd 64
#define NEGV -1000000000.0f

typedef unsigned long long u64;
typedef unsigned int u32;

// ---------------------------------------------------------------------------
// Scratch (device globals; only referenced from device code — selectors from host)
// ---------------------------------------------------------------------------
__device__ float g_q[Bb*Hh*Nn*Dd];     // [b,h,n,d]
__device__ float g_k[Bb*Hh*Nn*Dd];
__device__ float g_v[Bb*Hh*Nn*Dd];
__device__ float g_attn[Bb*Nn*Ee];     // flat [m = b*N+n, c = h*64+d]
__device__ unsigned char g_code[Bb*Nn*Nn];

__device__ __nv_bfloat16 gXh[3][Bb*Nn*Ee];   // query,key,value hi
__device__ __nv_bfloat16 gXl[3][Bb*Nn*Ee];   // lo
__device__ __nv_bfloat16 gWh[4][Ee*Ee];      // Wq,Wk,Wv,Wo hi
__device__ __nv_bfloat16 gWl[4][Ee*Ee];
__device__ __nv_bfloat16 gAh[Bb*Nn*Ee];      // attn flat hi
__device__ __nv_bfloat16 gAl[Bb*Nn*Ee];

// ---------------------------------------------------------------------------
// Small PTX helpers
// ---------------------------------------------------------------------------
__device__ __forceinline__ unsigned smem_u32(const void* p) {
    unsigned a;
    asm("{ .reg .u64 t; cvta.to.shared.u64 t, %1; cvt.u32.u64 %0, t; }"
        : "=r"(a) : "l"(p));
    return a;
}
__device__ __forceinline__ void cpasync16(unsigned dst, const void* src) {
    asm volatile("cp.async.ca.shared.global [%0], [%1], 16;" :: "r"(dst), "l"(src));
}
__device__ __forceinline__ void cpcommit() {
    asm volatile("cp.async.commit_group;" ::: "memory");
}
template<int N> __device__ __forceinline__ void cpwait() {
    asm volatile("cp.async.wait_group %0;" :: "n"(N) : "memory");
}
__device__ __forceinline__ void mma16816(float* c, const u32* a, const u32* b) {
    asm volatile("mma.sync.aligned.m16n8k16.row.col.f32.bf16.bf16.f32 "
        "{%0,%1,%2,%3}, {%4,%5,%6,%7}, {%8,%9}, {%0,%1,%2,%3};"
        : "+f"(c[0]), "+f"(c[1]), "+f"(c[2]), "+f"(c[3])
        : "r"(a[0]), "r"(a[1]), "r"(a[2]), "r"(a[3]), "r"(b[0]), "r"(b[1]));
}
// f32x2 helpers for flash (kept from R4 — flash measured slightly faster)
__device__ __forceinline__ void fma2(u64& d, u64 a, u64 b) {
    asm("fma.rn.f32x2 %0, %1, %2, %3;" : "=l"(d) : "l"(a), "l"(b), "l"(d));
}
__device__ __forceinline__ void mul2(u64& d, u64 a, u64 b) {
    asm("mul.rn.f32x2 %0, %1, %2;" : "=l"(d) : "l"(a), "l"(b));
}
__device__ __forceinline__ u64 pack2f(float lo, float hi) {
    u64 r; asm("mov.b64 %0, {%1,%2};" : "=l"(r) : "f"(lo), "f"(hi)); return r;
}
__device__ __forceinline__ float2 unpack2(u64 v) {
    float2 f; asm("mov.b64 {%0,%1}, %2;" : "=f"(f.x), "=f"(f.y) : "l"(v)); return f;
}

// ---------------------------------------------------------------------------
// Mask precompute
// ---------------------------------------------------------------------------
__device__ __forceinline__ unsigned char code_one(float d, int mk, int i, int j) {
    if (mk == 0) return (unsigned char)255;
    if (i == 0 || j == 0) return (unsigned char)0;
    unsigned char c = 0;
    c += (d >= 0.2f); c += (d >= 0.3f); c += (d >= 0.4f); c += (d >= 0.5f);
    c += (d >= 0.6f); c += (d >= 0.7f); c += (d >= 0.8f); c += (d >= 0.9f);
    return c;
}

__global__ __launch_bounds__(256) void code_kernel(const float* __restrict__ dist,
                                                   const int* __restrict__ mask) {
    int t = blockIdx.x * blockDim.x + threadIdx.x;
    int base = t * 4;
    int rem = base & (Nn*Nn - 1);
    int i = rem >> 10;
    int j0 = rem & (Nn - 1);
    float4 dv = *(const float4*)(dist + base);
    int4  mv = *(const int4*)(mask + base);
    uchar4 o;
    o.x = code_one(dv.x, mv.x, i, j0 + 0);
    o.y = code_one(dv.y, mv.y, i, j0 + 1);
    o.z = code_one(dv.z, mv.z, i, j0 + 2);
    o.w = code_one(dv.w, mv.w, i, j0 + 3);
    *(uchar4*)(g_code + base) = o;
}

// ---------------------------------------------------------------------------
// fp32 -> bf16 hi/lo split. which: 0..2 -> gX, 3..6 -> gW[which-3], 7 -> g_attn->gA
// ---------------------------------------------------------------------------
__device__ __forceinline__ void split4(float4 v, __nv_bfloat16* hp, __nv_bfloat16* lp,
                                       int t) {
    __nv_bfloat16 hx = __float2bfloat16(v.x);
    __nv_bfloat16 hy = __float2bfloat16(v.y);
    __nv_bfloat16 hz = __float2bfloat16(v.z);
    __nv_bfloat16 hw = __float2bfloat16(v.w);
    __nv_bfloat16 lx = __float2bfloat16(v.x - __bfloat162float(hx));
    __nv_bfloat16 ly = __float2bfloat16(v.y - __bfloat162float(hy));
    __nv_bfloat16 lz = __float2bfloat16(v.z - __bfloat162float(hz));
    __nv_bfloat16 lw = __float2bfloat16(v.w - __bfloat162float(hw));
    __nv_bfloat162* h2 = (__nv_bfloat162*)hp;
    __nv_bfloat162* l2 = (__nv_bfloat162*)lp;
    h2[2*t+0] = __nv_bfloat162(hx, hy);
    h2[2*t+1] = __nv_bfloat162(hz, hw);
    l2[2*t+0] = __nv_bfloat162(lx, ly);
    l2[2*t+1] = __nv_bfloat162(lz, lw);
}

__global__ __launch_bounds__(256) void split_kernel(const float* __restrict__ src,
                                                    int which, int n4) {
    int t = blockIdx.x * blockDim.x + threadIdx.x;
    if (t >= n4) return;
    const float* s = (which == 7) ? g_attn : src;
    float4 v = ((const float4*)s)[t];
    __nv_bfloat16* hp = (which < 3) ? gXh[which] : (which < 7) ? gWh[which - 3] : gAh;
    __nv_bfloat16* lp = (which < 3) ? gXl[which] : (which < 7) ? gWl[which - 3] : gAl;
    split4(v, hp, lp, t);
}

// ---------------------------------------------------------------------------
// HMMA split-bf16 GEMM: out = A[8192,512] . W[512,512]^T + bias
// CTA = 256 thr (8 warps, 2x4), 128x128 output tile, K chunks of 32,
// cp.async double-buffered. Smem rows stride 40 ushorts (conflict-free LDS).
// a_sel: 0..2 -> gX, 3 -> gA.  b_sel: 0..3 -> gW.
// out_mode: 0/1/2 -> scatter g_q/g_k/g_v [b,h,n,d]; 3 -> flat outext [m,512].
// ---------------------------------------------------------------------------
#define TSTRIDE 40                  // ushorts per smem row
#define TILE_US (128 * TSTRIDE)     // 5120 ushorts per (buf,hi/lo) tile
#define WOFF_US (4 * TILE_US)       // W region starts after A's 4 tiles
#define GEMM_SMEM_BYTES (8 * TILE_US * 2)   // 81920

__global__ __launch_bounds__(256, 2) void gemm_mma(const __nv_bfloat16* __restrict__ dummy,
                                                   const float* __restrict__ bias,
                                                   float* __restrict__ outext,
                                                   int a_sel, int b_sel, int out_mode) {
    extern __shared__ unsigned short gsm[];
    unsigned sbase = smem_u32(gsm);

    const __nv_bfloat16* Ahg = (a_sel < 3) ? gXh[a_sel] : gAh;
    const __nv_bfloat16* Alg = (a_sel < 3) ? gXl[a_sel] : gAl;
    const __nv_bfloat16* Whg = gWh[b_sel];
    const __nv_bfloat16* Wlg = gWl[b_sel];
    float* out = (out_mode == 0) ? g_q : (out_mode == 1) ? g_k
                 : (out_mode == 2) ? g_v : outext;

    int tid = threadIdx.x;
    int wid = tid >> 5, lane = tid & 31;
    int wr = wid >> 2, wc = wid & 3;            // warp 2x4
    int gid = lane >> 2, tig = lane & 3;
    int m0 = blockIdx.x * 128, n0 = blockIdx.y * 128;

    // per-thread load indices (2 x 16B per tile per chunk)
    int id0 = tid, id1 = 256 + tid;
    int r0 = id0 >> 2, c80 = (id0 & 3) * 8;
    int r1 = id1 >> 2, c81 = (id1 & 3) * 8;

    float c[4][4][4];
    #pragma unroll
    for (int mt = 0; mt < 4; mt++)
        #pragma unroll
        for (int nt = 0; nt < 4; nt++)
            #pragma unroll
            for (int q = 0; q < 4; q++) c[mt][nt][q] = 0.0f;

    auto load_chunk = [&](int kc, int buf) {
        int kb = kc * 32;
        {
            long a0 = (long)(m0 + r0) * Ee + kb + c80;
            long a1 = (long)(m0 + r1) * Ee + kb + c81;
            unsigned d0 = sbase + ((buf * 2 + 0) * TILE_US + r0 * TSTRIDE + c80) * 2;
            unsigned d1 = sbase + ((buf * 2 + 0) * TILE_US + r1 * TSTRIDE + c81) * 2;
            unsigned e0 = sbase + ((buf * 2 + 1) * TILE_US + r0 * TSTRIDE + c80) * 2;
            unsigned e1 = sbase + ((buf * 2 + 1) * TILE_US + r1 * TSTRIDE + c81) * 2;
            cpasync16(d0, Ahg + a0); cpasync16(d1, Ahg + a1);
            cpasync16(e0, Alg + a0); cpasync16(e1, Alg + a1);
        }
        {
            long w0 = (long)(n0 + r0) * Ee + kb + c80;
            long w1 = (long)(n0 + r1) * Ee + kb + c81;
            unsigned d0 = sbase + (WOFF_US + (buf * 2 + 0) * TILE_US + r0 * TSTRIDE + c80) * 2;
            unsigned d1 = sbase + (WOFF_US + (buf * 2 + 0) * TILE_US + r1 * TSTRIDE + c81) * 2;
            unsigned e0 = sbase + (WOFF_US + (buf * 2 + 1) * TILE_US + r0 * TSTRIDE + c80) * 2;
            unsigned e1 = sbase + (WOFF_US + (buf * 2 + 1) * TILE_US + r1 * TSTRIDE + c81) * 2;
            cpasync16(d0, Whg + w0); cpasync16(d1, Whg + w1);
            cpasync16(e0, Wlg + w0); cpasync16(e1, Wlg + w1);
        }
        cpcommit();
    };

    load_chunk(0, 0);

    for (int kc = 0; kc < 16; kc++) {
        int buf = kc & 1;
        if (kc < 15) load_chunk(kc + 1, buf ^ 1);
        if (kc < 15) cpwait<1>(); else cpwait<0>();
        __syncthreads();

        const unsigned short* sAh = gsm + (buf * 2 + 0) * TILE_US;
        const unsigned short* sAl = gsm + (buf * 2 + 1) * TILE_US;
        const unsigned short* sWh = gsm + WOFF_US + (buf * 2 + 0) * TILE_US;
        const unsigned short* sWl = gsm + WOFF_US + (buf * 2 + 1) * TILE_US;

        #pragma unroll
        for (int ks = 0; ks < 2; ks++) {
            int k0 = ks * 16 + tig * 2;
            u32 bh[4][2], bl[4][2];
            #pragma unroll
            for (int nt = 0; nt < 4; nt++) {
                int off = (wc * 32 + nt * 8 + gid) * TSTRIDE + k0;
                bh[nt][0] = *(const u32*)(sWh + off);
                bh[nt][1] = *(const u32*)(sWh + off + 8);
                bl[nt][0] = *(const u32*)(sWl + off);
                bl[nt][1] = *(const u32*)(sWl + off + 8);
            }
            #pragma unroll
            for (int mt = 0; mt < 4; mt++) {
                int off = (wr * 64 + mt * 16 + gid) * TSTRIDE + k0;
                u32 ah[4], al[4];
                ah[0] = *(const u32*)(sAh + off);
                ah[1] = *(const u32*)(sAh + off + 8 * TSTRIDE);
                ah[2] = *(const u32*)(sAh + off + 8);
                ah[3] = *(const u32*)(sAh + off + 8 * TSTRIDE + 8);
                al[0] = *(const u32*)(sAl + off);
                al[1] = *(const u32*)(sAl + off + 8 * TSTRIDE);
                al[2] = *(const u32*)(sAl + off + 8);
                al[3] = *(const u32*)(sAl + off + 8 * TSTRIDE + 8);
                #pragma unroll
                for (int nt = 0; nt < 4; nt++) {
                    mma16816(c[mt][nt], ah, bh[nt]);
                    mma16816(c[mt][nt], ah, bl[nt]);
                    mma16816(c[mt][nt], al, bh[nt]);
                }
            }
        }
        __syncthreads();
    }

    // Epilogue
    #pragma unroll
    for (int mt = 0; mt < 4; mt++) {
        #pragma unroll
        for (int nt = 0; nt < 4; nt++) {
            int row = m0 + wr * 64 + mt * 16 + gid;
            int col = n0 + wc * 32 + nt * 8 + tig * 2;
            float b0v = bias[col], b1v = bias[col + 1];
            float2 v0 = make_float2(c[mt][nt][0] + b0v, c[mt][nt][1] + b1v);
            float2 v1 = make_float2(c[mt][nt][2] + b0v, c[mt][nt][3] + b1v);
            if (out_mode < 3) {
                int h = col >> 6, d = col & 63;
                int b_ = row >> 10, n = row & (Nn - 1);
                float* p0 = out + ((((b_ << 3) + h) << 10) + n) * 64 + d;
                float* p1 = out + ((((b_ << 3) + h) << 10) + (n + 8)) * 64 + d;
                // row+8 changes n only (rows within a 128-tile never cross batch)
                *(float2*)p0 = v0;
                *(float2*)p1 = v1;
            } else {
                *(float2*)(out + (long)row * Ee + col) = v0;
                *(float2*)(out + (long)(row + 8) * Ee + col) = v1;
            }
        }
    }
}

// ---------------------------------------------------------------------------
// Flash attention (R4 version, f32x2-packed, verbatim)
// ---------------------------------------------------------------------------
#define ROWU 33
#define ROWF 66
#define FL_QP 0
#define FL_KP (64 * ROWU)
#define FL_VT (2 * 64 * ROWU)
#define FL_PT (3 * 64 * ROWU)
#define FL_CS_BYTES (4 * 64 * ROWU * 8)
#define FL_SMEM (FL_CS_BYTES + 64 * 64)

__global__ __launch_bounds__(256) void flash_kernel() {
    extern __shared__ u64 smu[];
    u64* Qp = smu + FL_QP;
    u64* Kp = smu + FL_KP;
    u64* Vt = smu + FL_VT;
    u64* Pt = smu + FL_PT;
    float* Qf = (float*)Qp;
    float* Kf = (float*)Kp;
    float* Vf = (float*)Vt;
    float* Pf = (float*)Pt;
    unsigned char* Cs = (unsigned char*)smu + FL_CS_BYTES;

    int rb = blockIdx.x, h = blockIdx.y, b = blockIdx.z;
    const float* Qg = g_q + (((b * Hh + h) * Nn + rb * 64) * Dd);
    const float* Kg = g_k + ((b * Hh + h) * Nn) * Dd;
    const float* Vg = g_v + ((b * Hh + h) * Nn) * Dd;
    const unsigned char* code = g_code + (b * Nn + rb * 64) * Nn;

    int tid = threadIdx.x;
    int ty = tid >> 4, tx = tid & 15;

    #pragma unroll
    for (int l = 0; l < 4; l++) {
        int idx = tid + l * 256;
        int r = idx >> 4;
        int d0 = (idx & 15) << 2;
        float4 q4 = *(const float4*)(Qg + r * 64 + d0);
        *(float2*)(Qf + r * ROWF + d0 + 0) = make_float2(q4.x, q4.y);
        *(float2*)(Qf + r * ROWF + d0 + 2) = make_float2(q4.z, q4.w);
    }

    u64 acc[4][4];
    #pragma unroll
    for (int i = 0; i < 4; i++)
        #pragma unroll
        for (int j = 0; j < 4; j++) acc[i][j] = 0ull;
    float m_i[4], l_i[4];
    #pragma unroll
    for (int i = 0; i < 4; i++) { m_i[i] = -1e30f; l_i[i] = 0.0f; }

    for (int kb = 0; kb < Nn / 64; kb++) {
        __syncthreads();
        #pragma unroll
        for (int l = 0; l < 4; l++) {
            int idx = tid + l * 256;
            int cc = idx >> 4;
            int d0 = (idx & 15) << 2;
            float4 k4 = *(const float4*)(Kg + (kb * 64 + cc) * 64 + d0);
            *(float2*)(Kf + cc * ROWF + d0 + 0) = make_float2(k4.x, k4.y);
            *(float2*)(Kf + cc * ROWF + d0 + 2) = make_float2(k4.z, k4.w);
            float4 v4 = *(const float4*)(Vg + (kb * 64 + cc) * 64 + d0);
            Vf[(d0 + 0) * ROWF + cc] = v4.x;
            Vf[(d0 + 1) * ROWF + cc] = v4.y;
            Vf[(d0 + 2) * ROWF + cc] = v4.z;
            Vf[(d0 + 3) * ROWF + cc] = v4.w;
        }
        {
            int r = tid >> 2;
            int s4 = (tid & 3) << 4;
            *(uint4*)(Cs + r * 64 + s4) = *(const uint4*)(code + r * Nn + kb * 64 + s4);
        }
        __syncthreads();

        u64 s2[4][4];
        #pragma unroll
        for (int i = 0; i < 4; i++)
            #pragma unroll
            for (int j = 0; j < 4; j++) s2[i][j] = 0ull;
        #pragma unroll
        for (int d2 = 0; d2 < 32; d2++) {
            u64 q2[4], k2[4];
            #pragma unroll
            for (int i = 0; i < 4; i++) q2[i] = Qp[(ty * 4 + i) * ROWU + d2];
            #pragma unroll
            for (int j = 0; j < 4; j++) k2[j] = Kp[(tx + 16 * j) * ROWU + d2];
            #pragma unroll
            for (int i = 0; i < 4; i++)
                #pragma unroll
                for (int j = 0; j < 4; j++)
                    fma2(s2[i][j], q2[i], k2[j]);
        }

        float s[4][4];
        #pragma unroll
        for (int i = 0; i < 4; i++)
            #pragma unroll
            for (int j = 0; j < 4; j++) {
                float2 f = unpack2(s2[i][j]);
                float v = (f.x + f.y) * 0.125f;
                unsigned cd = Cs[(ty * 4 + i) * 64 + tx + 16 * j];
                s[i][j] = ((unsigned)h >= cd) ? v : NEGV;
            }

        float corr[4], ps[4];
        #pragma unroll
        for (int i = 0; i < 4; i++) {
            float r = fmaxf(fmaxf(s[i][0], s[i][1]), fmaxf(s[i][2], s[i][3]));
            #pragma unroll
            for (int o = 8; o > 0; o >>= 1)
                r = fmaxf(r, __shfl_xor_sync(0xffffffffu, r, o));
            float mn = fmaxf(m_i[i], r);
            corr[i] = __expf(m_i[i] - mn);
            m_i[i] = mn;
            ps[i] = 0.0f;
        }
        #pragma unroll
        for (int i = 0; i < 4; i++)
            #pragma unroll
            for (int j = 0; j < 4; j++) {
                float p = __expf(s[i][j] - m_i[i]);
                ps[i] += p;
                Pf[(ty * 4 + i) * ROWF + tx + 16 * j] = p;
            }
        #pragma unroll
        for (int i = 0; i < 4; i++) {
            float r = ps[i];
            #pragma unroll
            for (int o = 8; o > 0; o >>= 1)
                r += __shfl_xor_sync(0xffffffffu, r, o);
            l_i[i] = l_i[i] * corr[i] + r;
            u64 c2 = pack2f(corr[i], corr[i]);
            #pragma unroll
            for (int j = 0; j < 4; j++) mul2(acc[i][j], acc[i][j], c2);
        }
        __syncthreads();

        #pragma unroll
        for (int c2 = 0; c2 < 32; c2++) {
            u64 p2[4], v2[4];
            #pragma unroll
            for (int i = 0; i < 4; i++) p2[i] = Pt[(ty * 4 + i) * ROWU + c2];
            #pragma unroll
            for (int j = 0; j < 4; j++) v2[j] = Vt[(tx + 16 * j) * ROWU + c2];
            #pragma unroll
            for (int i = 0; i < 4; i++)
                #pragma unroll
                for (int j = 0; j < 4; j++)
                    fma2(acc[i][j], p2[i], v2[j]);
        }
    }

    #pragma unroll
    for (int i = 0; i < 4; i++) {
        float inv = 1.0f / l_i[i];
        int n = rb * 64 + ty * 4 + i;
        float* op = g_attn + ((b << 10) + n) * Ee + (h << 6);
        #pragma unroll
        for (int j = 0; j < 4; j++) {
            float2 f = unpack2(acc[i][j]);
            op[tx + 16 * j] = (f.x + f.y) * inv;
        }
    }
}

// ---------------------------------------------------------------------------
extern "C" void kernel_launch(void* const* d_in, const int* in_sizes, int n_in,
                              void* d_out, int out_size) {
    const float* query = (const float*)d_in[0];
    const float* key   = (const float*)d_in[1];
    const float* value = (const float*)d_in[2];
    const float* dist  = (const float*)d_in[3];
    const int*   mask  = (const int*)d_in[4];
    const float* Wq = (const float*)d_in[5];
    const float* bq = (const float*)d_in[6];
    const float* Wk = (const float*)d_in[7];
    const float* bk = (const float*)d_in[8];
    const float* Wv = (const float*)d_in[9];
    const float* bv = (const float*)d_in[10];
    const float* Wo = (const float*)d_in[11];
    const float* bo = (const float*)d_in[12];
    float* out = (float*)d_out;

    cudaFuncSetAttribute(flash_kernel, cudaFuncAttributeMaxDynamicSharedMemorySize, FL_SMEM);
    cudaFuncSetAttribute(gemm_mma, cudaFuncAttributeMaxDynamicSharedMemorySize, GEMM_SMEM_BYTES);

    // 1) mask code precompute
    code_kernel<<<(Bb * Nn * Nn) / (4 * 256), 256>>>(dist, mask);

    // 2) bf16 hi/lo splits (activations + weights)
    const int NX4 = (Bb * Nn * Ee) / 4;   // 1,048,576
    const int NW4 = (Ee * Ee) / 4;        // 65,536
    split_kernel<<<NX4 / 256, 256>>>(query, 0, NX4);
    split_kernel<<<NX4 / 256, 256>>>(key,   1, NX4);
    split_kernel<<<NX4 / 256, 256>>>(value, 2, NX4);
    split_kernel<<<NW4 / 256, 256>>>(Wq, 3, NW4);
    split_kernel<<<NW4 / 256, 256>>>(Wk, 4, NW4);
    split_kernel<<<NW4 / 256, 256>>>(Wv, 5, NW4);
    split_kernel<<<NW4 / 256, 256>>>(Wo, 6, NW4);

    // 3) Q/K/V projections on HMMA (scatter into g_q/g_k/g_v)
    dim3 ggrid((Bb * Nn) / 128, Ee / 128);    // (64, 4)
    gemm_mma<<<ggrid, 256, GEMM_SMEM_BYTES>>>(nullptr, bq, nullptr, 0, 0, 0);
    gemm_mma<<<ggrid, 256, GEMM_SMEM_BYTES>>>(nullptr, bk, nullptr, 1, 1, 1);
    gemm_mma<<<ggrid, 256, GEMM_SMEM_BYTES>>>(nullptr, bv, nullptr, 2, 2, 2);

    // 4) flash attention -> flat g_attn
    flash_kernel<<<dim3(Nn / 64, Hh, Bb), 256, FL_SMEM>>>();

    // 5) split attn output, then output projection on HMMA
    split_kernel<<<NX4 / 256, 256>>>(nullptr, 7, NX4);
    gemm_mma<<<ggrid, 256, GEMM_SMEM_BYTES>>>(nullptr, bo, out, 3, 3, 3);
}

// round 6
// speedup vs baseline: 2.5197x; 1.7279x over previous
#include <cuda_runtime.h>
#include <cuda_bf16.h>

#define Bb 8
#define Nn 1024
#define Ee 512
#define Hh 8
#define Dd 64
#define NEGV -1000000000.0f

typedef unsigned long long u64;
typedef unsigned int u32;

// ---------------------------------------------------------------------------
// Scratch (device globals; referenced only from device code)
// ---------------------------------------------------------------------------
__device__ unsigned char g_code[Bb*Nn*Nn];

__device__ __nv_bfloat16 gXh[3][Bb*Nn*Ee];   // query,key,value inputs hi
__device__ __nv_bfloat16 gXl[3][Bb*Nn*Ee];   // lo
__device__ __nv_bfloat16 gWh[4][Ee*Ee];      // Wq,Wk,Wv,Wo hi
__device__ __nv_bfloat16 gWl[4][Ee*Ee];

__device__ __nv_bfloat16 gQh[Bb*Hh*Nn*Dd];   // projected Q [b,h,n,d]
__device__ __nv_bfloat16 gQl[Bb*Hh*Nn*Dd];
__device__ __nv_bfloat16 gKh[Bb*Hh*Nn*Dd];   // projected K [b,h,n,d]
__device__ __nv_bfloat16 gKl[Bb*Hh*Nn*Dd];
__device__ __nv_bfloat16 gVth[Bb*Hh*Dd*Nn];  // projected V TRANSPOSED [b,h,d,n]
__device__ __nv_bfloat16 gVtl[Bb*Hh*Dd*Nn];
__device__ __nv_bfloat16 gAh[Bb*Nn*Ee];      // attn out flat [m, h*64+d]
__device__ __nv_bfloat16 gAl[Bb*Nn*Ee];

// ---------------------------------------------------------------------------
// PTX helpers
// ---------------------------------------------------------------------------
__device__ __forceinline__ unsigned smem_u32(const void* p) {
    unsigned a;
    asm("{ .reg .u64 t; cvta.to.shared.u64 t, %1; cvt.u32.u64 %0, t; }"
        : "=r"(a) : "l"(p));
    return a;
}
__device__ __forceinline__ void cpasync16(unsigned dst, const void* src) {
    asm volatile("cp.async.ca.shared.global [%0], [%1], 16;" :: "r"(dst), "l"(src));
}
__device__ __forceinline__ void cpcommit() {
    asm volatile("cp.async.commit_group;" ::: "memory");
}
template<int N> __device__ __forceinline__ void cpwait() {
    asm volatile("cp.async.wait_group %0;" :: "n"(N) : "memory");
}
__device__ __forceinline__ void mma16816(float* c, const u32* a, const u32* b) {
    asm volatile("mma.sync.aligned.m16n8k16.row.col.f32.bf16.bf16.f32 "
        "{%0,%1,%2,%3}, {%4,%5,%6,%7}, {%8,%9}, {%0,%1,%2,%3};"
        : "+f"(c[0]), "+f"(c[1]), "+f"(c[2]), "+f"(c[3])
        : "r"(a[0]), "r"(a[1]), "r"(a[2]), "r"(a[3]), "r"(b[0]), "r"(b[1]));
}
__device__ __forceinline__ u32 packbf(float lo, float hi) {
    __nv_bfloat162 t = __floats2bfloat162_rn(lo, hi);   // x=lo, y=hi
    return *(u32*)&t;
}
__device__ __forceinline__ float lo_f(u32 v) { return __uint_as_float(v << 16); }
__device__ __forceinline__ float hi_f(u32 v) { return __uint_as_float(v & 0xffff0000u); }

// ---------------------------------------------------------------------------
// Mask precompute
// ---------------------------------------------------------------------------
__device__ __forceinline__ unsigned char code_one(float d, int mk, int i, int j) {
    if (mk == 0) return (unsigned char)255;
    if (i == 0 || j == 0) return (unsigned char)0;
    unsigned char c = 0;
    c += (d >= 0.2f); c += (d >= 0.3f); c += (d >= 0.4f); c += (d >= 0.5f);
    c += (d >= 0.6f); c += (d >= 0.7f); c += (d >= 0.8f); c += (d >= 0.9f);
    return c;
}

__global__ __launch_bounds__(256) void code_kernel(const float* __restrict__ dist,
                                                   const int* __restrict__ mask) {
    int t = blockIdx.x * blockDim.x + threadIdx.x;
    int base = t * 4;
    int rem = base & (Nn*Nn - 1);
    int i = rem >> 10;
    int j0 = rem & (Nn - 1);
    float4 dv = *(const float4*)(dist + base);
    int4  mv = *(const int4*)(mask + base);
    uchar4 o;
    o.x = code_one(dv.x, mv.x, i, j0 + 0);
    o.y = code_one(dv.y, mv.y, i, j0 + 1);
    o.z = code_one(dv.z, mv.z, i, j0 + 2);
    o.w = code_one(dv.w, mv.w, i, j0 + 3);
    *(uchar4*)(g_code + base) = o;
}

// ---------------------------------------------------------------------------
// fp32 -> bf16 hi/lo split of inputs/weights. which: 0..2 -> gX, 3..6 -> gW
// ---------------------------------------------------------------------------
__global__ __launch_bounds__(256) void split_kernel(const float* __restrict__ src,
                                                    int which, int n4) {
    int t = blockIdx.x * blockDim.x + threadIdx.x;
    if (t >= n4) return;
    float4 v = ((const float4*)src)[t];
    __nv_bfloat16* hp = (which < 3) ? gXh[which] : gWh[which - 3];
    __nv_bfloat16* lp = (which < 3) ? gXl[which] : gWl[which - 3];
    u32* h2 = (u32*)hp;
    u32* l2 = (u32*)lp;
    u32 hxy = packbf(v.x, v.y), hzw = packbf(v.z, v.w);
    h2[2*t+0] = hxy;
    h2[2*t+1] = hzw;
    l2[2*t+0] = packbf(v.x - lo_f(hxy), v.y - hi_f(hxy));
    l2[2*t+1] = packbf(v.z - lo_f(hzw), v.w - hi_f(hzw));
}

// ---------------------------------------------------------------------------
// HMMA split-bf16 GEMM: out = A[8192,512] . W[512,512]^T + bias
// a_sel: 0..2 -> gX[a_sel], 3 -> gA (attn flat).  b_sel: 0..3 -> gW.
// out_mode: 0 -> gQh/gQl [b,h,n,d]; 1 -> gKh/gKl [b,h,n,d];
//           2 -> gVth/gVtl [b,h,d,n] (transposed); 3 -> fp32 flat outext.
// ---------------------------------------------------------------------------
#define TSTRIDE 40
#define TILE_US (128 * TSTRIDE)
#define WOFF_US (4 * TILE_US)
#define GEMM_SMEM_BYTES (8 * TILE_US * 2)

__global__ __launch_bounds__(256, 2) void gemm_mma(const float* __restrict__ bias,
                                                   float* __restrict__ outext,
                                                   int a_sel, int b_sel, int out_mode) {
    extern __shared__ unsigned short gsm[];
    unsigned sbase = smem_u32(gsm);

    const __nv_bfloat16* Ahg = (a_sel < 3) ? gXh[a_sel] : gAh;
    const __nv_bfloat16* Alg = (a_sel < 3) ? gXl[a_sel] : gAl;
    const __nv_bfloat16* Whg = gWh[b_sel];
    const __nv_bfloat16* Wlg = gWl[b_sel];

    int tid = threadIdx.x;
    int wid = tid >> 5, lane = tid & 31;
    int wr = wid >> 2, wc = wid & 3;
    int gid = lane >> 2, tig = lane & 3;
    int m0 = blockIdx.x * 128, n0 = blockIdx.y * 128;

    int id0 = tid, id1 = 256 + tid;
    int r0 = id0 >> 2, c80 = (id0 & 3) * 8;
    int r1 = id1 >> 2, c81 = (id1 & 3) * 8;

    float c[4][4][4];
    #pragma unroll
    for (int mt = 0; mt < 4; mt++)
        #pragma unroll
        for (int nt = 0; nt < 4; nt++)
            #pragma unroll
            for (int q = 0; q < 4; q++) c[mt][nt][q] = 0.0f;

    auto load_chunk = [&](int kc, int buf) {
        int kb = kc * 32;
        {
            int a0 = (m0 + r0) * Ee + kb + c80;
            int a1 = (m0 + r1) * Ee + kb + c81;
            unsigned d0 = sbase + ((buf * 2 + 0) * TILE_US + r0 * TSTRIDE + c80) * 2;
            unsigned d1 = sbase + ((buf * 2 + 0) * TILE_US + r1 * TSTRIDE + c81) * 2;
            unsigned e0 = sbase + ((buf * 2 + 1) * TILE_US + r0 * TSTRIDE + c80) * 2;
            unsigned e1 = sbase + ((buf * 2 + 1) * TILE_US + r1 * TSTRIDE + c81) * 2;
            cpasync16(d0, Ahg + a0); cpasync16(d1, Ahg + a1);
            cpasync16(e0, Alg + a0); cpasync16(e1, Alg + a1);
        }
        {
            int w0 = (n0 + r0) * Ee + kb + c80;
            int w1 = (n0 + r1) * Ee + kb + c81;
            unsigned d0 = sbase + (WOFF_US + (buf * 2 + 0) * TILE_US + r0 * TSTRIDE + c80) * 2;
            unsigned d1 = sbase + (WOFF_US + (buf * 2 + 0) * TILE_US + r1 * TSTRIDE + c81) * 2;
            unsigned e0 = sbase + (WOFF_US + (buf * 2 + 1) * TILE_US + r0 * TSTRIDE + c80) * 2;
            unsigned e1 = sbase + (WOFF_US + (buf * 2 + 1) * TILE_US + r1 * TSTRIDE + c81) * 2;
            cpasync16(d0, Whg + w0); cpasync16(d1, Whg + w1);
            cpasync16(e0, Wlg + w0); cpasync16(e1, Wlg + w1);
        }
        cpcommit();
    };

    load_chunk(0, 0);

    for (int kc = 0; kc < 16; kc++) {
        int buf = kc & 1;
        if (kc < 15) load_chunk(kc + 1, buf ^ 1);
        if (kc < 15) cpwait<1>(); else cpwait<0>();
        __syncthreads();

        const unsigned short* sAh = gsm + (buf * 2 + 0) * TILE_US;
        const unsigned short* sAl = gsm + (buf * 2 + 1) * TILE_US;
        const unsigned short* sWh = gsm + WOFF_US + (buf * 2 + 0) * TILE_US;
        const unsigned short* sWl = gsm + WOFF_US + (buf * 2 + 1) * TILE_US;

        #pragma unroll
        for (int ks = 0; ks < 2; ks++) {
            int k0 = ks * 16 + tig * 2;
            u32 bh[4][2], bl[4][2];
            #pragma unroll
            for (int nt = 0; nt < 4; nt++) {
                int off = (wc * 32 + nt * 8 + gid) * TSTRIDE + k0;
                bh[nt][0] = *(const u32*)(sWh + off);
                bh[nt][1] = *(const u32*)(sWh + off + 8);
                bl[nt][0] = *(const u32*)(sWl + off);
                bl[nt][1] = *(const u32*)(sWl + off + 8);
            }
            #pragma unroll
            for (int mt = 0; mt < 4; mt++) {
                int off = (wr * 64 + mt * 16 + gid) * TSTRIDE + k0;
                u32 ah[4], al[4];
                ah[0] = *(const u32*)(sAh + off);
                ah[1] = *(const u32*)(sAh + off + 8 * TSTRIDE);
                ah[2] = *(const u32*)(sAh + off + 8);
                ah[3] = *(const u32*)(sAh + off + 8 * TSTRIDE + 8);
                al[0] = *(const u32*)(sAl + off);
                al[1] = *(const u32*)(sAl + off + 8 * TSTRIDE);
                al[2] = *(const u32*)(sAl + off + 8);
                al[3] = *(const u32*)(sAl + off + 8 * TSTRIDE + 8);
                #pragma unroll
                for (int nt = 0; nt < 4; nt++) {
                    mma16816(c[mt][nt], ah, bh[nt]);
                    mma16816(c[mt][nt], ah, bl[nt]);
                    mma16816(c[mt][nt], al, bh[nt]);
                }
            }
        }
        __syncthreads();
    }

    // Epilogue
    #pragma unroll
    for (int mt = 0; mt < 4; mt++) {
        #pragma unroll
        for (int nt = 0; nt < 4; nt++) {
            int row = m0 + wr * 64 + mt * 16 + gid;
            int col = n0 + wc * 32 + nt * 8 + tig * 2;
            float b0v = bias[col], b1v = bias[col + 1];
            float v00 = c[mt][nt][0] + b0v, v01 = c[mt][nt][1] + b1v;
            float v10 = c[mt][nt][2] + b0v, v11 = c[mt][nt][3] + b1v;
            int b_ = row >> 10, n = row & (Nn - 1);
            int hh = col >> 6, d = col & 63;
            if (out_mode <= 1) {
                __nv_bfloat16* Hp = (out_mode == 0) ? gQh : gKh;
                __nv_bfloat16* Lp = (out_mode == 0) ? gQl : gKl;
                int a0 = (((b_ << 3) + hh) * Nn + n) * Dd + d;
                int a1 = a0 + 8 * Dd;
                u32 h0 = packbf(v00, v01), h1 = packbf(v10, v11);
                *(u32*)(Hp + a0) = h0;
                *(u32*)(Hp + a1) = h1;
                *(u32*)(Lp + a0) = packbf(v00 - lo_f(h0), v01 - hi_f(h0));
                *(u32*)(Lp + a1) = packbf(v10 - lo_f(h1), v11 - hi_f(h1));
            } else if (out_mode == 2) {
                // transposed [b,h,d,n]
                int base = ((b_ << 3) + hh) * Dd;
                int i00 = (base + d) * Nn + n;
                int i01 = (base + d + 1) * Nn + n;
                __nv_bfloat16 h00 = __float2bfloat16(v00);
                __nv_bfloat16 h01 = __float2bfloat16(v01);
                __nv_bfloat16 h10 = __float2bfloat16(v10);
                __nv_bfloat16 h11 = __float2bfloat16(v11);
                gVth[i00]     = h00;
                gVth[i01]     = h01;
                gVth[i00 + 8] = h10;
                gVth[i01 + 8] = h11;
                gVtl[i00]     = __float2bfloat16(v00 - __bfloat162float(h00));
                gVtl[i01]     = __float2bfloat16(v01 - __bfloat162float(h01));
                gVtl[i00 + 8] = __float2bfloat16(v10 - __bfloat162float(h10));
                gVtl[i01 + 8] = __float2bfloat16(v11 - __bfloat162float(h11));
            } else {
                *(float2*)(outext + row * Ee + col) = make_float2(v00, v01);
                *(float2*)(outext + (row + 8) * Ee + col) = make_float2(v10, v11);
            }
        }
    }
}

// ---------------------------------------------------------------------------
// HMMA flash attention. CTA = 128 q-rows (8 warps x 16 rows), key blocks of 64.
// QK^T: (Qh+Ql)(Kh+Kl) 3-term; PV: P split in registers x (Vh+Vl) 3-term.
// Writes gAh/gAl flat [m, h*64+d] directly.
// ---------------------------------------------------------------------------
#define FTS 72                        // ushorts per smem row
#define FQ_H 0
#define FQ_L (128 * FTS)              // 9216
#define FK_H (2 * 128 * FTS)          // 18432
#define FK_L (FK_H + 64 * FTS)
#define FV_H (FK_H + 2 * 64 * FTS)
#define FV_L (FK_H + 3 * 64 * FTS)
#define FCS_B ((FK_H + 4 * 64 * FTS) * 2)   // byte offset 73728
#define FLASH_SMEM (FCS_B + 128 * 64)        // 81920

__global__ __launch_bounds__(256, 2) void flash_mma() {
    extern __shared__ unsigned short fsm[];
    unsigned sbase = smem_u32(fsm);
    unsigned char* CsP = (unsigned char*)fsm + FCS_B;

    int rb = blockIdx.x, h = blockIdx.y, b = blockIdx.z;
    int tid = threadIdx.x, wid = tid >> 5, lane = tid & 31;
    int gid = lane >> 2, tig = lane & 3;
    int bh = b * Hh + h;

    const __nv_bfloat16* Qhg = gQh + (bh * Nn + rb * 128) * Dd;
    const __nv_bfloat16* Qlg = gQl + (bh * Nn + rb * 128) * Dd;
    const __nv_bfloat16* Khg = gKh + bh * Nn * Dd;
    const __nv_bfloat16* Klg = gKl + bh * Nn * Dd;
    const __nv_bfloat16* Vhg = gVth + bh * Dd * Nn;
    const __nv_bfloat16* Vlg = gVtl + bh * Dd * Nn;
    const unsigned char* codeg = g_code + (b * Nn + rb * 128) * Nn;

    // Q tiles (loaded once)
    #pragma unroll
    for (int l = 0; l < 4; l++) {
        int idx = tid + l * 256;
        int row = idx >> 3, c8 = (idx & 7) * 8;
        cpasync16(sbase + (FQ_H + row * FTS + c8) * 2, Qhg + row * Dd + c8);
        cpasync16(sbase + (FQ_L + row * FTS + c8) * 2, Qlg + row * Dd + c8);
    }
    cpcommit();

    float co[8][4];
    #pragma unroll
    for (int dt = 0; dt < 8; dt++)
        #pragma unroll
        for (int q = 0; q < 4; q++) co[dt][q] = 0.0f;
    float m0r = -1e30f, m1r = -1e30f, l0r = 0.0f, l1r = 0.0f;

    for (int kb = 0; kb < 16; kb++) {
        __syncthreads();
        #pragma unroll
        for (int l = 0; l < 2; l++) {
            int idx = tid + l * 256;
            int row = idx >> 3, c8 = (idx & 7) * 8;
            cpasync16(sbase + (FK_H + row * FTS + c8) * 2, Khg + (kb * 64 + row) * Dd + c8);
            cpasync16(sbase + (FK_L + row * FTS + c8) * 2, Klg + (kb * 64 + row) * Dd + c8);
            cpasync16(sbase + (FV_H + row * FTS + c8) * 2, Vhg + row * Nn + kb * 64 + c8);
            cpasync16(sbase + (FV_L + row * FTS + c8) * 2, Vlg + row * Nn + kb * 64 + c8);
            int rowc = idx >> 2, c16 = (idx & 3) * 16;
            cpasync16(sbase + FCS_B + rowc * 64 + c16, codeg + rowc * Nn + kb * 64 + c16);
        }
        cpcommit();
        cpwait<0>();
        __syncthreads();

        // ---- S = Q.K^T (3-term split) ----
        float sc[8][4];
        #pragma unroll
        for (int nt = 0; nt < 8; nt++)
            #pragma unroll
            for (int q = 0; q < 4; q++) sc[nt][q] = 0.0f;

        int qr = (wid * 16 + gid) * FTS;
        #pragma unroll
        for (int ks = 0; ks < 4; ks++) {
            int k0 = ks * 16 + tig * 2;
            u32 ah[4], al[4];
            ah[0] = *(const u32*)(fsm + FQ_H + qr + k0);
            ah[1] = *(const u32*)(fsm + FQ_H + qr + 8 * FTS + k0);
            ah[2] = *(const u32*)(fsm + FQ_H + qr + k0 + 8);
            ah[3] = *(const u32*)(fsm + FQ_H + qr + 8 * FTS + k0 + 8);
            al[0] = *(const u32*)(fsm + FQ_L + qr + k0);
            al[1] = *(const u32*)(fsm + FQ_L + qr + 8 * FTS + k0);
            al[2] = *(const u32*)(fsm + FQ_L + qr + k0 + 8);
            al[3] = *(const u32*)(fsm + FQ_L + qr + 8 * FTS + k0 + 8);
            #pragma unroll
            for (int nt = 0; nt < 8; nt++) {
                int kr = (nt * 8 + gid) * FTS + k0;
                u32 bh2[2], bl2[2];
                bh2[0] = *(const u32*)(fsm + FK_H + kr);
                bh2[1] = *(const u32*)(fsm + FK_H + kr + 8);
                bl2[0] = *(const u32*)(fsm + FK_L + kr);
                bl2[1] = *(const u32*)(fsm + FK_L + kr + 8);
                mma16816(sc[nt], ah, bh2);
                mma16816(sc[nt], ah, bl2);
                mma16816(sc[nt], al, bh2);
            }
        }

        // ---- mask + scale ----
        int crow = (wid * 16 + gid) * 64;
        #pragma unroll
        for (int nt = 0; nt < 8; nt++) {
            unsigned short cw0 = *(const unsigned short*)(CsP + crow + nt * 8 + tig * 2);
            unsigned short cw1 = *(const unsigned short*)(CsP + crow + 8 * 64 + nt * 8 + tig * 2);
            sc[nt][0] = ((unsigned)h >= (cw0 & 255u)) ? sc[nt][0] * 0.125f : NEGV;
            sc[nt][1] = ((unsigned)h >= (cw0 >> 8))   ? sc[nt][1] * 0.125f : NEGV;
            sc[nt][2] = ((unsigned)h >= (cw1 & 255u)) ? sc[nt][2] * 0.125f : NEGV;
            sc[nt][3] = ((unsigned)h >= (cw1 >> 8))   ? sc[nt][3] * 0.125f : NEGV;
        }

        // ---- online softmax (row0 = gid, row1 = gid+8 of warp strip) ----
        float rm0 = -1e30f, rm1 = -1e30f;
        #pragma unroll
        for (int nt = 0; nt < 8; nt++) {
            rm0 = fmaxf(rm0, fmaxf(sc[nt][0], sc[nt][1]));
            rm1 = fmaxf(rm1, fmaxf(sc[nt][2], sc[nt][3]));
        }
        rm0 = fmaxf(rm0, __shfl_xor_sync(0xffffffffu, rm0, 1));
        rm0 = fmaxf(rm0, __shfl_xor_sync(0xffffffffu, rm0, 2));
        rm1 = fmaxf(rm1, __shfl_xor_sync(0xffffffffu, rm1, 1));
        rm1 = fmaxf(rm1, __shfl_xor_sync(0xffffffffu, rm1, 2));
        float mn0 = fmaxf(m0r, rm0), mn1 = fmaxf(m1r, rm1);
        float corr0 = __expf(m0r - mn0), corr1 = __expf(m1r - mn1);
        m0r = mn0; m1r = mn1;

        float ps0 = 0.0f, ps1 = 0.0f;
        #pragma unroll
        for (int nt = 0; nt < 8; nt++) {
            sc[nt][0] = __expf(sc[nt][0] - mn0);
            sc[nt][1] = __expf(sc[nt][1] - mn0);
            sc[nt][2] = __expf(sc[nt][2] - mn1);
            sc[nt][3] = __expf(sc[nt][3] - mn1);
            ps0 += sc[nt][0] + sc[nt][1];
            ps1 += sc[nt][2] + sc[nt][3];
        }
        ps0 += __shfl_xor_sync(0xffffffffu, ps0, 1);
        ps0 += __shfl_xor_sync(0xffffffffu, ps0, 2);
        ps1 += __shfl_xor_sync(0xffffffffu, ps1, 1);
        ps1 += __shfl_xor_sync(0xffffffffu, ps1, 2);
        l0r = l0r * corr0 + ps0;
        l1r = l1r * corr1 + ps1;

        #pragma unroll
        for (int dt = 0; dt < 8; dt++) {
            co[dt][0] *= corr0; co[dt][1] *= corr0;
            co[dt][2] *= corr1; co[dt][3] *= corr1;
        }

        // ---- O += P.V (P split in registers) ----
        #pragma unroll
        for (int kc = 0; kc < 4; kc++) {
            u32 pah[4], pal[4];
            pah[0] = packbf(sc[2*kc][0],   sc[2*kc][1]);
            pah[1] = packbf(sc[2*kc][2],   sc[2*kc][3]);
            pah[2] = packbf(sc[2*kc+1][0], sc[2*kc+1][1]);
            pah[3] = packbf(sc[2*kc+1][2], sc[2*kc+1][3]);
            pal[0] = packbf(sc[2*kc][0]   - lo_f(pah[0]), sc[2*kc][1]   - hi_f(pah[0]));
            pal[1] = packbf(sc[2*kc][2]   - lo_f(pah[1]), sc[2*kc][3]   - hi_f(pah[1]));
            pal[2] = packbf(sc[2*kc+1][0] - lo_f(pah[2]), sc[2*kc+1][1] - hi_f(pah[2]));
            pal[3] = packbf(sc[2*kc+1][2] - lo_f(pah[3]), sc[2*kc+1][3] - hi_f(pah[3]));
            #pragma unroll
            for (int dt = 0; dt < 8; dt++) {
                int vr = (dt * 8 + gid) * FTS + kc * 16 + tig * 2;
                u32 vh2[2], vl2[2];
                vh2[0] = *(const u32*)(fsm + FV_H + vr);
                vh2[1] = *(const u32*)(fsm + FV_H + vr + 8);
                vl2[0] = *(const u32*)(fsm + FV_L + vr);
                vl2[1] = *(const u32*)(fsm + FV_L + vr + 8);
                mma16816(co[dt], pah, vh2);
                mma16816(co[dt], pah, vl2);
                mma16816(co[dt], pal, vh2);
            }
        }
    }

    // ---- epilogue: O / l -> gAh/gAl flat [m, h*64+d] ----
    float inv0 = 1.0f / l0r, inv1 = 1.0f / l1r;
    int nrow = rb * 128 + wid * 16 + gid;
    int a0base = ((b << 10) + nrow) * Ee + (h << 6);
    int a1base = a0base + 8 * Ee;
    #pragma unroll
    for (int dt = 0; dt < 8; dt++) {
        int d = dt * 8 + tig * 2;
        float v00 = co[dt][0] * inv0, v01 = co[dt][1] * inv0;
        float v10 = co[dt][2] * inv1, v11 = co[dt][3] * inv1;
        u32 h0 = packbf(v00, v01), h1 = packbf(v10, v11);
        *(u32*)(gAh + a0base + d) = h0;
        *(u32*)(gAh + a1base + d) = h1;
        *(u32*)(gAl + a0base + d) = packbf(v00 - lo_f(h0), v01 - hi_f(h0));
        *(u32*)(gAl + a1base + d) = packbf(v10 - lo_f(h1), v11 - hi_f(h1));
    }
}

// ---------------------------------------------------------------------------
extern "C" void kernel_launch(void* const* d_in, const int* in_sizes, int n_in,
                              void* d_out, int out_size) {
    const float* query = (const float*)d_in[0];
    const float* key   = (const float*)d_in[1];
    const float* value = (const float*)d_in[2];
    const float* dist  = (const float*)d_in[3];
    const int*   mask  = (const int*)d_in[4];
    const float* Wq = (const float*)d_in[5];
    const float* bq = (const float*)d_in[6];
    const float* Wk = (const float*)d_in[7];
    const float* bk = (const float*)d_in[8];
    const float* Wv = (const float*)d_in[9];
    const float* bv = (const float*)d_in[10];
    const float* Wo = (const float*)d_in[11];
    const float* bo = (const float*)d_in[12];
    float* out = (float*)d_out;

    cudaFuncSetAttribute(gemm_mma, cudaFuncAttributeMaxDynamicSharedMemorySize, GEMM_SMEM_BYTES);
    cudaFuncSetAttribute(flash_mma, cudaFuncAttributeMaxDynamicSharedMemorySize, FLASH_SMEM);

    // 1) mask code precompute
    code_kernel<<<(Bb * Nn * Nn) / (4 * 256), 256>>>(dist, mask);

    // 2) bf16 hi/lo splits (inputs + weights)
    const int NX4 = (Bb * Nn * Ee) / 4;
    const int NW4 = (Ee * Ee) / 4;
    split_kernel<<<NX4 / 256, 256>>>(query, 0, NX4);
    split_kernel<<<NX4 / 256, 256>>>(key,   1, NX4);
    split_kernel<<<NX4 / 256, 256>>>(value, 2, NX4);
    split_kernel<<<NW4 / 256, 256>>>(Wq, 3, NW4);
    split_kernel<<<NW4 / 256, 256>>>(Wk, 4, NW4);
    split_kernel<<<NW4 / 256, 256>>>(Wv, 5, NW4);
    split_kernel<<<NW4 / 256, 256>>>(Wo, 6, NW4);

    // 3) Q/K/V projections (HMMA, epilogue emits split-bf16; V transposed)
    dim3 ggrid((Bb * Nn) / 128, Ee / 128);
    gemm_mma<<<ggrid, 256, GEMM_SMEM_BYTES>>>(bq, nullptr, 0, 0, 0);
    gemm_mma<<<ggrid, 256, GEMM_SMEM_BYTES>>>(bk, nullptr, 1, 1, 1);
    gemm_mma<<<ggrid, 256, GEMM_SMEM_BYTES>>>(bv, nullptr, 2, 2, 2);

    // 4) HMMA flash attention -> gAh/gAl
    flash_mma<<<dim3(Nn / 128, Hh, Bb), 256, FLASH_SMEM>>>();

    // 5) output projection (fp32 flat out)
    gemm_mma<<<ggrid, 256, GEMM_SMEM_BYTES>>>(bo, out, 3, 3, 3);
}

// round 7
// speedup vs baseline: 2.6912x; 1.0681x over previous
#include <cuda_runtime.h>
#include <cuda_bf16.h>

#define Bb 8
#define Nn 1024
#define Ee 512
#define Hh 8
#define Dd 64
#define NEGV -1000000000.0f

typedef unsigned long long u64;
typedef unsigned int u32;

// ---------------------------------------------------------------------------
// Scratch (device globals; referenced only from device code)
// ---------------------------------------------------------------------------
__device__ unsigned char g_code[Bb*Nn*Nn];

__device__ __nv_bfloat16 gXh[3][Bb*Nn*Ee];   // query,key,value inputs hi
__device__ __nv_bfloat16 gXl[3][Bb*Nn*Ee];   // lo
__device__ __nv_bfloat16 gWh[4][Ee*Ee];      // Wq,Wk,Wv,Wo hi
__device__ __nv_bfloat16 gWl[4][Ee*Ee];

__device__ __nv_bfloat16 gQh[Bb*Hh*Nn*Dd];   // projected Q [b,h,n,d]
__device__ __nv_bfloat16 gQl[Bb*Hh*Nn*Dd];
__device__ __nv_bfloat16 gKh[Bb*Hh*Nn*Dd];   // projected K [b,h,n,d]
__device__ __nv_bfloat16 gKl[Bb*Hh*Nn*Dd];
__device__ __nv_bfloat16 gVth[Bb*Hh*Dd*Nn];  // projected V TRANSPOSED [b,h,d,n]
__device__ __nv_bfloat16 gVtl[Bb*Hh*Dd*Nn];
__device__ __nv_bfloat16 gAh[Bb*Nn*Ee];      // attn out flat [m, h*64+d]
__device__ __nv_bfloat16 gAl[Bb*Nn*Ee];

// ---------------------------------------------------------------------------
// PTX helpers
// ---------------------------------------------------------------------------
__device__ __forceinline__ unsigned smem_u32(const void* p) {
    unsigned a;
    asm("{ .reg .u64 t; cvta.to.shared.u64 t, %1; cvt.u32.u64 %0, t; }"
        : "=r"(a) : "l"(p));
    return a;
}
__device__ __forceinline__ void cpasync16(unsigned dst, const void* src) {
    asm volatile("cp.async.ca.shared.global [%0], [%1], 16;" :: "r"(dst), "l"(src));
}
__device__ __forceinline__ void cpcommit() {
    asm volatile("cp.async.commit_group;" ::: "memory");
}
template<int N> __device__ __forceinline__ void cpwait() {
    asm volatile("cp.async.wait_group %0;" :: "n"(N) : "memory");
}
__device__ __forceinline__ void mma16816(float* c, const u32* a, const u32* b) {
    asm volatile("mma.sync.aligned.m16n8k16.row.col.f32.bf16.bf16.f32 "
        "{%0,%1,%2,%3}, {%4,%5,%6,%7}, {%8,%9}, {%0,%1,%2,%3};"
        : "+f"(c[0]), "+f"(c[1]), "+f"(c[2]), "+f"(c[3])
        : "r"(a[0]), "r"(a[1]), "r"(a[2]), "r"(a[3]), "r"(b[0]), "r"(b[1]));
}
__device__ __forceinline__ void ldsm_x4(u32* r, unsigned addr) {
    asm volatile("ldmatrix.sync.aligned.m8n8.x4.shared.b16 {%0,%1,%2,%3}, [%4];"
        : "=r"(r[0]), "=r"(r[1]), "=r"(r[2]), "=r"(r[3]) : "r"(addr));
}
__device__ __forceinline__ void ldsm_x2(u32* r, unsigned addr) {
    asm volatile("ldmatrix.sync.aligned.m8n8.x2.shared.b16 {%0,%1}, [%2];"
        : "=r"(r[0]), "=r"(r[1]) : "r"(addr));
}
__device__ __forceinline__ u32 packbf(float lo, float hi) {
    __nv_bfloat162 t = __floats2bfloat162_rn(lo, hi);
    return *(u32*)&t;
}
__device__ __forceinline__ float lo_f(u32 v) { return __uint_as_float(v << 16); }
__device__ __forceinline__ float hi_f(u32 v) { return __uint_as_float(v & 0xffff0000u); }

// ---------------------------------------------------------------------------
// Mask precompute
// ---------------------------------------------------------------------------
__device__ __forceinline__ unsigned char code_one(float d, int mk, int i, int j) {
    if (mk == 0) return (unsigned char)255;
    if (i == 0 || j == 0) return (unsigned char)0;
    unsigned char c = 0;
    c += (d >= 0.2f); c += (d >= 0.3f); c += (d >= 0.4f); c += (d >= 0.5f);
    c += (d >= 0.6f); c += (d >= 0.7f); c += (d >= 0.8f); c += (d >= 0.9f);
    return c;
}

__global__ __launch_bounds__(256) void code_kernel(const float* __restrict__ dist,
                                                   const int* __restrict__ mask) {
    int t = blockIdx.x * blockDim.x + threadIdx.x;
    int base = t * 4;
    int rem = base & (Nn*Nn - 1);
    int i = rem >> 10;
    int j0 = rem & (Nn - 1);
    float4 dv = *(const float4*)(dist + base);
    int4  mv = *(const int4*)(mask + base);
    uchar4 o;
    o.x = code_one(dv.x, mv.x, i, j0 + 0);
    o.y = code_one(dv.y, mv.y, i, j0 + 1);
    o.z = code_one(dv.z, mv.z, i, j0 + 2);
    o.w = code_one(dv.w, mv.w, i, j0 + 3);
    *(uchar4*)(g_code + base) = o;
}

// ---------------------------------------------------------------------------
// fp32 -> bf16 hi/lo splits (fused: X batch via grid.y, W batch via grid.y)
// ---------------------------------------------------------------------------
__device__ __forceinline__ void split_store(float4 v, __nv_bfloat16* hp,
                                            __nv_bfloat16* lp, int t) {
    u32* h2 = (u32*)hp;
    u32* l2 = (u32*)lp;
    u32 hxy = packbf(v.x, v.y), hzw = packbf(v.z, v.w);
    h2[2*t+0] = hxy;
    h2[2*t+1] = hzw;
    l2[2*t+0] = packbf(v.x - lo_f(hxy), v.y - hi_f(hxy));
    l2[2*t+1] = packbf(v.z - lo_f(hzw), v.w - hi_f(hzw));
}

__global__ __launch_bounds__(256) void split_x_kernel(const float* __restrict__ s0,
                                                      const float* __restrict__ s1,
                                                      const float* __restrict__ s2) {
    int which = blockIdx.y;
    const float* src = (which == 0) ? s0 : (which == 1) ? s1 : s2;
    int t = blockIdx.x * blockDim.x + threadIdx.x;
    float4 v = ((const float4*)src)[t];
    split_store(v, gXh[which], gXl[which], t);
}

__global__ __launch_bounds__(256) void split_w_kernel(const float* __restrict__ s0,
                                                      const float* __restrict__ s1,
                                                      const float* __restrict__ s2,
                                                      const float* __restrict__ s3) {
    int which = blockIdx.y;
    const float* src = (which == 0) ? s0 : (which == 1) ? s1
                      : (which == 2) ? s2 : s3;
    int t = blockIdx.x * blockDim.x + threadIdx.x;
    float4 v = ((const float4*)src)[t];
    split_store(v, gWh[which], gWl[which], t);
}

// ---------------------------------------------------------------------------
// HMMA split-bf16 GEMM. fused=1: blockIdx.z = 0/1/2 selects Q/K/V projection;
// fused=0: output projection (a=gA, b=Wo, fp32 flat out).
// ---------------------------------------------------------------------------
#define TSTRIDE 40
#define TILE_US (128 * TSTRIDE)
#define WOFF_US (4 * TILE_US)
#define GEMM_SMEM_BYTES (8 * TILE_US * 2)

__global__ __launch_bounds__(256, 2) void gemm_mma(const float* __restrict__ bias0,
                                                   const float* __restrict__ bias1,
                                                   const float* __restrict__ bias2,
                                                   float* __restrict__ outext,
                                                   int fused) {
    extern __shared__ unsigned short gsm[];
    unsigned sbase = smem_u32(gsm);

    int sel = fused ? blockIdx.z : 3;
    const __nv_bfloat16* Ahg = (sel < 3) ? gXh[sel] : gAh;
    const __nv_bfloat16* Alg = (sel < 3) ? gXl[sel] : gAl;
    const __nv_bfloat16* Whg = gWh[sel];
    const __nv_bfloat16* Wlg = gWl[sel];
    const float* bias = (sel == 0 || sel == 3) ? bias0 : (sel == 1) ? bias1 : bias2;
    int out_mode = sel;

    int tid = threadIdx.x;
    int wid = tid >> 5, lane = tid & 31;
    int wr = wid >> 2, wc = wid & 3;
    int gid = lane >> 2, tig = lane & 3;
    int m0 = blockIdx.x * 128, n0 = blockIdx.y * 128;

    int id0 = tid, id1 = 256 + tid;
    int r0 = id0 >> 2, c80 = (id0 & 3) * 8;
    int r1 = id1 >> 2, c81 = (id1 & 3) * 8;

    // ldmatrix per-lane address components
    int rA = lane & 15, kA = (lane >> 4) * 8;          // A-frag x4
    int rB = lane & 7,  kB = ((lane >> 3) & 1) * 8;    // B-frag x2

    float c[4][4][4];
    #pragma unroll
    for (int mt = 0; mt < 4; mt++)
        #pragma unroll
        for (int nt = 0; nt < 4; nt++)
            #pragma unroll
            for (int q = 0; q < 4; q++) c[mt][nt][q] = 0.0f;

    auto load_chunk = [&](int kc, int buf) {
        int kb = kc * 32;
        {
            int a0 = (m0 + r0) * Ee + kb + c80;
            int a1 = (m0 + r1) * Ee + kb + c81;
            unsigned d0 = sbase + ((buf * 2 + 0) * TILE_US + r0 * TSTRIDE + c80) * 2;
            unsigned d1 = sbase + ((buf * 2 + 0) * TILE_US + r1 * TSTRIDE + c81) * 2;
            unsigned e0 = sbase + ((buf * 2 + 1) * TILE_US + r0 * TSTRIDE + c80) * 2;
            unsigned e1 = sbase + ((buf * 2 + 1) * TILE_US + r1 * TSTRIDE + c81) * 2;
            cpasync16(d0, Ahg + a0); cpasync16(d1, Ahg + a1);
            cpasync16(e0, Alg + a0); cpasync16(e1, Alg + a1);
        }
        {
            int w0 = (n0 + r0) * Ee + kb + c80;
            int w1 = (n0 + r1) * Ee + kb + c81;
            unsigned d0 = sbase + (WOFF_US + (buf * 2 + 0) * TILE_US + r0 * TSTRIDE + c80) * 2;
            unsigned d1 = sbase + (WOFF_US + (buf * 2 + 0) * TILE_US + r1 * TSTRIDE + c81) * 2;
            unsigned e0 = sbase + (WOFF_US + (buf * 2 + 1) * TILE_US + r0 * TSTRIDE + c80) * 2;
            unsigned e1 = sbase + (WOFF_US + (buf * 2 + 1) * TILE_US + r1 * TSTRIDE + c81) * 2;
            cpasync16(d0, Whg + w0); cpasync16(d1, Whg + w1);
            cpasync16(e0, Wlg + w0); cpasync16(e1, Wlg + w1);
        }
        cpcommit();
    };

    load_chunk(0, 0);

    for (int kc = 0; kc < 16; kc++) {
        int buf = kc & 1;
        if (kc < 15) load_chunk(kc + 1, buf ^ 1);
        if (kc < 15) cpwait<1>(); else cpwait<0>();
        __syncthreads();

        unsigned ah_us = (unsigned)((buf * 2 + 0) * TILE_US);
        unsigned al_us = (unsigned)((buf * 2 + 1) * TILE_US);
        unsigned wh_us = (unsigned)(WOFF_US + (buf * 2 + 0) * TILE_US);
        unsigned wl_us = (unsigned)(WOFF_US + (buf * 2 + 1) * TILE_US);

        #pragma unroll
        for (int ks = 0; ks < 2; ks++) {
            int k0 = ks * 16;
            u32 bh[4][2], bl[4][2];
            #pragma unroll
            for (int nt = 0; nt < 4; nt++) {
                unsigned boff = ((wc * 32 + nt * 8 + rB) * TSTRIDE + k0 + kB) * 2;
                ldsm_x2(bh[nt], sbase + (wh_us * 2) + boff);
                ldsm_x2(bl[nt], sbase + (wl_us * 2) + boff);
            }
            #pragma unroll
            for (int mt = 0; mt < 4; mt++) {
                unsigned aoff = ((wr * 64 + mt * 16 + rA) * TSTRIDE + k0 + kA) * 2;
                u32 ah[4], al[4];
                ldsm_x4(ah, sbase + (ah_us * 2) + aoff);
                ldsm_x4(al, sbase + (al_us * 2) + aoff);
                #pragma unroll
                for (int nt = 0; nt < 4; nt++) {
                    mma16816(c[mt][nt], ah, bh[nt]);
                    mma16816(c[mt][nt], ah, bl[nt]);
                    mma16816(c[mt][nt], al, bh[nt]);
                }
            }
        }
        __syncthreads();
    }

    // Epilogue
    #pragma unroll
    for (int mt = 0; mt < 4; mt++) {
        #pragma unroll
        for (int nt = 0; nt < 4; nt++) {
            int row = m0 + wr * 64 + mt * 16 + gid;
            int col = n0 + wc * 32 + nt * 8 + tig * 2;
            float b0v = bias[col], b1v = bias[col + 1];
            float v00 = c[mt][nt][0] + b0v, v01 = c[mt][nt][1] + b1v;
            float v10 = c[mt][nt][2] + b0v, v11 = c[mt][nt][3] + b1v;
            int b_ = row >> 10, n = row & (Nn - 1);
            int hh = col >> 6, d = col & 63;
            if (out_mode <= 1) {
                __nv_bfloat16* Hp = (out_mode == 0) ? gQh : gKh;
                __nv_bfloat16* Lp = (out_mode == 0) ? gQl : gKl;
                int a0 = (((b_ << 3) + hh) * Nn + n) * Dd + d;
                int a1 = a0 + 8 * Dd;
                u32 h0 = packbf(v00, v01), h1 = packbf(v10, v11);
                *(u32*)(Hp + a0) = h0;
                *(u32*)(Hp + a1) = h1;
                *(u32*)(Lp + a0) = packbf(v00 - lo_f(h0), v01 - hi_f(h0));
                *(u32*)(Lp + a1) = packbf(v10 - lo_f(h1), v11 - hi_f(h1));
            } else if (out_mode == 2) {
                int base = ((b_ << 3) + hh) * Dd;
                int i00 = (base + d) * Nn + n;
                int i01 = (base + d + 1) * Nn + n;
                __nv_bfloat16 h00 = __float2bfloat16(v00);
                __nv_bfloat16 h01 = __float2bfloat16(v01);
                __nv_bfloat16 h10 = __float2bfloat16(v10);
                __nv_bfloat16 h11 = __float2bfloat16(v11);
                gVth[i00]     = h00;
                gVth[i01]     = h01;
                gVth[i00 + 8] = h10;
                gVth[i01 + 8] = h11;
                gVtl[i00]     = __float2bfloat16(v00 - __bfloat162float(h00));
                gVtl[i01]     = __float2bfloat16(v01 - __bfloat162float(h01));
                gVtl[i00 + 8] = __float2bfloat16(v10 - __bfloat162float(h10));
                gVtl[i01 + 8] = __float2bfloat16(v11 - __bfloat162float(h11));
            } else {
                *(float2*)(outext + row * Ee + col) = make_float2(v00, v01);
                *(float2*)(outext + (row + 8) * Ee + col) = make_float2(v10, v11);
            }
        }
    }
}

// ---------------------------------------------------------------------------
// HMMA flash attention, double-buffered K/V, ldmatrix frags, direct-LDG mask.
// ---------------------------------------------------------------------------
#define FTS 72
#define FQ_H 0
#define FQ_L (128 * FTS)
#define FSTG0 (2 * 128 * FTS)                 // stage area start (ushorts)
#define FSTG_SZ (4 * 64 * FTS)                // per-stage ushorts (Kh,Kl,Vh,Vl)
#define FK_L_OFF (64 * FTS)
#define FV_H_OFF (2 * 64 * FTS)
#define FV_L_OFF (3 * 64 * FTS)
#define FLASH_SMEM ((FSTG0 + 2 * FSTG_SZ) * 2)   // 110592 bytes

__global__ __launch_bounds__(256, 2) void flash_mma() {
    extern __shared__ unsigned short fsm[];
    unsigned sbase = smem_u32(fsm);

    int rb = blockIdx.x, h = blockIdx.y, b = blockIdx.z;
    int tid = threadIdx.x, wid = tid >> 5, lane = tid & 31;
    int gid = lane >> 2, tig = lane & 3;
    int bh = b * Hh + h;

    const __nv_bfloat16* Qhg = gQh + (bh * Nn + rb * 128) * Dd;
    const __nv_bfloat16* Qlg = gQl + (bh * Nn + rb * 128) * Dd;
    const __nv_bfloat16* Khg = gKh + bh * Nn * Dd;
    const __nv_bfloat16* Klg = gKl + bh * Nn * Dd;
    const __nv_bfloat16* Vhg = gVth + bh * Dd * Nn;
    const __nv_bfloat16* Vlg = gVtl + bh * Dd * Nn;
    const unsigned char* codeg = g_code + (b * Nn + rb * 128) * Nn;

    int rA = lane & 15, kA = (lane >> 4) * 8;
    int rB = lane & 7,  kB = ((lane >> 3) & 1) * 8;

    auto load_kv = [&](int kb, int s) {
        unsigned stg = (unsigned)(FSTG0 + s * FSTG_SZ);
        #pragma unroll
        for (int l = 0; l < 2; l++) {
            int idx = tid + l * 256;
            int row = idx >> 3, c8 = (idx & 7) * 8;
            unsigned so = (row * FTS + c8) * 2;
            cpasync16(sbase + stg * 2 + so, Khg + (kb * 64 + row) * Dd + c8);
            cpasync16(sbase + (stg + FK_L_OFF) * 2 + so, Klg + (kb * 64 + row) * Dd + c8);
            cpasync16(sbase + (stg + FV_H_OFF) * 2 + so, Vhg + row * Nn + kb * 64 + c8);
            cpasync16(sbase + (stg + FV_L_OFF) * 2 + so, Vlg + row * Nn + kb * 64 + c8);
        }
    };

    // Q tiles + stage 0 in one group
    #pragma unroll
    for (int l = 0; l < 4; l++) {
        int idx = tid + l * 256;
        int row = idx >> 3, c8 = (idx & 7) * 8;
        cpasync16(sbase + (FQ_H + row * FTS + c8) * 2, Qhg + row * Dd + c8);
        cpasync16(sbase + (FQ_L + row * FTS + c8) * 2, Qlg + row * Dd + c8);
    }
    load_kv(0, 0);
    cpcommit();

    unsigned qh_base = sbase + ((FQ_H + (wid * 16 + rA) * FTS + kA) * 2);
    unsigned ql_base = sbase + ((FQ_L + (wid * 16 + rA) * FTS + kA) * 2);

    float co[8][4];
    #pragma unroll
    for (int dt = 0; dt < 8; dt++)
        #pragma unroll
        for (int q = 0; q < 4; q++) co[dt][q] = 0.0f;
    float m0r = -1e30f, m1r = -1e30f, l0r = 0.0f, l1r = 0.0f;

    int crow0 = wid * 16 + gid;
    const unsigned char* cp0 = codeg + crow0 * Nn + tig * 2;
    const unsigned char* cp1 = codeg + (crow0 + 8) * Nn + tig * 2;

    for (int kb = 0; kb < 16; kb++) {
        int buf = kb & 1;
        __syncthreads();                       // prev compute done before reuse
        if (kb < 15) { load_kv(kb + 1, buf ^ 1); cpcommit(); }
        if (kb < 15) cpwait<1>(); else cpwait<0>();
        __syncthreads();

        // mask codes via direct LDG (L2), overlap with MMAs below
        unsigned short cw0[8], cw1[8];
        #pragma unroll
        for (int nt = 0; nt < 8; nt++) {
            cw0[nt] = *(const unsigned short*)(cp0 + kb * 64 + nt * 8);
            cw1[nt] = *(const unsigned short*)(cp1 + kb * 64 + nt * 8);
        }

        unsigned stg = (unsigned)(FSTG0 + buf * FSTG_SZ);

        // ---- S = Q.K^T (3-term) ----
        float sc[8][4];
        #pragma unroll
        for (int nt = 0; nt < 8; nt++)
            #pragma unroll
            for (int q = 0; q < 4; q++) sc[nt][q] = 0.0f;

        #pragma unroll
        for (int ks = 0; ks < 4; ks++) {
            u32 ah[4], al[4];
            ldsm_x4(ah, qh_base + ks * 32);
            ldsm_x4(al, ql_base + ks * 32);
            #pragma unroll
            for (int nt = 0; nt < 8; nt++) {
                unsigned kaddr = sbase + ((stg + (nt * 8 + rB) * FTS + ks * 16 + kB) * 2);
                u32 bh2[2], bl2[2];
                ldsm_x2(bh2, kaddr);
                ldsm_x2(bl2, kaddr + FK_L_OFF * 2);
                mma16816(sc[nt], ah, bh2);
                mma16816(sc[nt], ah, bl2);
                mma16816(sc[nt], al, bh2);
            }
        }

        // ---- mask + scale ----
        #pragma unroll
        for (int nt = 0; nt < 8; nt++) {
            sc[nt][0] = ((unsigned)h >= (cw0[nt] & 255u)) ? sc[nt][0] * 0.125f : NEGV;
            sc[nt][1] = ((unsigned)h >= (cw0[nt] >> 8))   ? sc[nt][1] * 0.125f : NEGV;
            sc[nt][2] = ((unsigned)h >= (cw1[nt] & 255u)) ? sc[nt][2] * 0.125f : NEGV;
            sc[nt][3] = ((unsigned)h >= (cw1[nt] >> 8))   ? sc[nt][3] * 0.125f : NEGV;
        }

        // ---- online softmax ----
        float rm0 = -1e30f, rm1 = -1e30f;
        #pragma unroll
        for (int nt = 0; nt < 8; nt++) {
            rm0 = fmaxf(rm0, fmaxf(sc[nt][0], sc[nt][1]));
            rm1 = fmaxf(rm1, fmaxf(sc[nt][2], sc[nt][3]));
        }
        rm0 = fmaxf(rm0, __shfl_xor_sync(0xffffffffu, rm0, 1));
        rm0 = fmaxf(rm0, __shfl_xor_sync(0xffffffffu, rm0, 2));
        rm1 = fmaxf(rm1, __shfl_xor_sync(0xffffffffu, rm1, 1));
        rm1 = fmaxf(rm1, __shfl_xor_sync(0xffffffffu, rm1, 2));
        float mn0 = fmaxf(m0r, rm0), mn1 = fmaxf(m1r, rm1);
        float corr0 = __expf(m0r - mn0), corr1 = __expf(m1r - mn1);
        m0r = mn0; m1r = mn1;

        float ps0 = 0.0f, ps1 = 0.0f;
        #pragma unroll
        for (int nt = 0; nt < 8; nt++) {
            sc[nt][0] = __expf(sc[nt][0] - mn0);
            sc[nt][1] = __expf(sc[nt][1] - mn0);
            sc[nt][2] = __expf(sc[nt][2] - mn1);
            sc[nt][3] = __expf(sc[nt][3] - mn1);
            ps0 += sc[nt][0] + sc[nt][1];
            ps1 += sc[nt][2] + sc[nt][3];
        }
        ps0 += __shfl_xor_sync(0xffffffffu, ps0, 1);
        ps0 += __shfl_xor_sync(0xffffffffu, ps0, 2);
        ps1 += __shfl_xor_sync(0xffffffffu, ps1, 1);
        ps1 += __shfl_xor_sync(0xffffffffu, ps1, 2);
        l0r = l0r * corr0 + ps0;
        l1r = l1r * corr1 + ps1;

        #pragma unroll
        for (int dt = 0; dt < 8; dt++) {
            co[dt][0] *= corr0; co[dt][1] *= corr0;
            co[dt][2] *= corr1; co[dt][3] *= corr1;
        }

        // ---- O += P.V (P split in registers) ----
        #pragma unroll
        for (int kc = 0; kc < 4; kc++) {
            u32 pah[4], pal[4];
            pah[0] = packbf(sc[2*kc][0],   sc[2*kc][1]);
            pah[1] = packbf(sc[2*kc][2],   sc[2*kc][3]);
            pah[2] = packbf(sc[2*kc+1][0], sc[2*kc+1][1]);
            pah[3] = packbf(sc[2*kc+1][2], sc[2*kc+1][3]);
            pal[0] = packbf(sc[2*kc][0]   - lo_f(pah[0]), sc[2*kc][1]   - hi_f(pah[0]));
            pal[1] = packbf(sc[2*kc][2]   - lo_f(pah[1]), sc[2*kc][3]   - hi_f(pah[1]));
            pal[2] = packbf(sc[2*kc+1][0] - lo_f(pah[2]), sc[2*kc+1][1] - hi_f(pah[2]));
            pal[3] = packbf(sc[2*kc+1][2] - lo_f(pah[3]), sc[2*kc+1][3] - hi_f(pah[3]));
            #pragma unroll
            for (int dt = 0; dt < 8; dt++) {
                unsigned vaddr = sbase + ((stg + FV_H_OFF + (dt * 8 + rB) * FTS
                                           + kc * 16 + kB) * 2);
                u32 vh2[2], vl2[2];
                ldsm_x2(vh2, vaddr);
                ldsm_x2(vl2, vaddr + (FV_L_OFF - FV_H_OFF) * 2);
                mma16816(co[dt], pah, vh2);
                mma16816(co[dt], pah, vl2);
                mma16816(co[dt], pal, vh2);
            }
        }
    }

    // ---- epilogue ----
    float inv0 = 1.0f / l0r, inv1 = 1.0f / l1r;
    int nrow = rb * 128 + wid * 16 + gid;
    int a0base = ((b << 10) + nrow) * Ee + (h << 6);
    int a1base = a0base + 8 * Ee;
    #pragma unroll
    for (int dt = 0; dt < 8; dt++) {
        int d = dt * 8 + tig * 2;
        float v00 = co[dt][0] * inv0, v01 = co[dt][1] * inv0;
        float v10 = co[dt][2] * inv1, v11 = co[dt][3] * inv1;
        u32 h0 = packbf(v00, v01), h1 = packbf(v10, v11);
        *(u32*)(gAh + a0base + d) = h0;
        *(u32*)(gAh + a1base + d) = h1;
        *(u32*)(gAl + a0base + d) = packbf(v00 - lo_f(h0), v01 - hi_f(h0));
        *(u32*)(gAl + a1base + d) = packbf(v10 - lo_f(h1), v11 - hi_f(h1));
    }
}

// ---------------------------------------------------------------------------
extern "C" void kernel_launch(void* const* d_in, const int* in_sizes, int n_in,
                              void* d_out, int out_size) {
    const float* query = (const float*)d_in[0];
    const float* key   = (const float*)d_in[1];
    const float* value = (const float*)d_in[2];
    const float* dist  = (const float*)d_in[3];
    const int*   mask  = (const int*)d_in[4];
    const float* Wq = (const float*)d_in[5];
    const float* bq = (const float*)d_in[6];
    const float* Wk = (const float*)d_in[7];
    const float* bk = (const float*)d_in[8];
    const float* Wv = (const float*)d_in[9];
    const float* bv = (const float*)d_in[10];
    const float* Wo = (const float*)d_in[11];
    const float* bo = (const float*)d_in[12];
    float* out = (float*)d_out;

    cudaFuncSetAttribute(gemm_mma, cudaFuncAttributeMaxDynamicSharedMemorySize, GEMM_SMEM_BYTES);
    cudaFuncSetAttribute(flash_mma, cudaFuncAttributeMaxDynamicSharedMemorySize, FLASH_SMEM);

    // 1) mask code precompute
    code_kernel<<<(Bb * Nn * Nn) / (4 * 256), 256>>>(dist, mask);

    // 2) fused bf16 hi/lo splits
    const int NX4 = (Bb * Nn * Ee) / 4;
    const int NW4 = (Ee * Ee) / 4;
    split_x_kernel<<<dim3(NX4 / 256, 3), 256>>>(query, key, value);
    split_w_kernel<<<dim3(NW4 / 256, 4), 256>>>(Wq, Wk, Wv, Wo);

    // 3) fused Q/K/V projections (grid.z selects)
    gemm_mma<<<dim3((Bb * Nn) / 128, Ee / 128, 3), 256, GEMM_SMEM_BYTES>>>(
        bq, bk, bv, nullptr, 1);

    // 4) HMMA flash attention -> gAh/gAl
    flash_mma<<<dim3(Nn / 128, Hh, Bb), 256, FLASH_SMEM>>>();

    // 5) output projection
    gemm_mma<<<dim3((Bb * Nn) / 128, Ee / 128, 1), 256, GEMM_SMEM_BYTES>>>(
        bo, nullptr, nullptr, out, 0);
}